// round 2
// baseline (speedup 1.0000x reference)
#include <cuda_runtime.h>

#define NBLOCKS 1184
#define NTHREADS 256

__device__ double g_partials[NBLOCKS];

__device__ __forceinline__ double warpReduceD(double v) {
    #pragma unroll
    for (int o = 16; o > 0; o >>= 1)
        v += __shfl_down_sync(0xffffffffu, v, o);
    return v;
}

// se3_log on (R[9] row-major, t[3]) -> xi[6] = [rho, phi]
__device__ __forceinline__ void se3_log_f(const float* R, const float* t, float* xi) {
    float tr = R[0] + R[4] + R[8];
    float c = 0.5f * (tr - 1.0f);
    c = fminf(fmaxf(c, -1.0f + 1e-7f), 1.0f - 1e-7f);
    float th = acosf(c);
    // sin(acos(c)) = sqrt(1-c^2), exact for th in [0, pi]
    float s = sqrtf(fmaxf(1.0f - c * c, 1e-20f));
    float factor = __fdividef(th, 2.0f * s);
    float px = factor * (R[7] - R[5]);
    float py = factor * (R[2] - R[6]);
    float pz = factor * (R[3] - R[1]);
    // |phi| == th analytically; clip guarantees th >= ~4.47e-4 so t2 >= 2e-7 > EPS
    float t2 = th * th;
    float D = __fdividef(1.0f, t2) - __fdividef(1.0f + c, 2.0f * th * s);
    // rho = t - 0.5*(phi x t) + D*(phi*(phi.t) - t2*t)
    float pd = px * t[0] + py * t[1] + pz * t[2];
    float cx = py * t[2] - pz * t[1];
    float cy = pz * t[0] - px * t[2];
    float cz = px * t[1] - py * t[0];
    xi[0] = t[0] - 0.5f * cx + D * (px * pd - t2 * t[0]);
    xi[1] = t[1] - 0.5f * cy + D * (py * pd - t2 * t[1]);
    xi[2] = t[2] - 0.5f * cz + D * (pz * pd - t2 * t[2]);
    xi[3] = px;
    xi[4] = py;
    xi[5] = pz;
}

__global__ void __launch_bounds__(NTHREADS)
se3_loss_main(const float* __restrict__ inp, const float* __restrict__ T,
              const float* __restrict__ P, int B) {
    __shared__ float sP[36];
    if (threadIdx.x < 36) sP[threadIdx.x] = P[threadIdx.x];
    __syncthreads();

    double acc = 0.0;
    for (int b = blockIdx.x * NTHREADS + threadIdx.x; b < B; b += NBLOCKS * NTHREADS) {
        // ---- load input row (6 floats, 8B-aligned) ----
        const float2* ip = (const float2*)(inp + 6 * (long)b);
        float2 a0 = ip[0], a1 = ip[1], a2 = ip[2];
        float r0i = a0.x, r1i = a0.y, r2i = a1.x;   // rho_in
        float x = a1.y, y = a2.x, z = a2.y;         // phi_in

        // ---- se3_exp(input) ----
        float t2 = x * x + y * y + z * z;
        bool small = t2 < 1e-8f;
        float t2s = small ? 1.0f : t2;
        float th = sqrtf(t2s);
        float s, co;
        __sincosf(th, &s, &co);
        float A  = small ? 1.0f - t2 * (1.0f / 6.0f)  : __fdividef(s, th);
        float Bc = small ? 0.5f - t2 * (1.0f / 24.0f) : __fdividef(1.0f - co, t2s);
        float Cc = small ? (1.0f / 6.0f) - t2 * (1.0f / 120.0f)
                         : __fdividef(th - s, t2s * th);
        // R1 = I + A*K + Bc*(pp^T - t2*I)
        float R1[9];
        R1[0] = 1.0f + Bc * (x * x - t2);
        R1[1] = Bc * x * y - A * z;
        R1[2] = Bc * x * z + A * y;
        R1[3] = Bc * x * y + A * z;
        R1[4] = 1.0f + Bc * (y * y - t2);
        R1[5] = Bc * y * z - A * x;
        R1[6] = Bc * x * z - A * y;
        R1[7] = Bc * y * z + A * x;
        R1[8] = 1.0f + Bc * (z * z - t2);
        // t1 = Jl(phi) @ rho = rho + Bc*(phi x rho) + Cc*(phi*(phi.rho) - t2*rho)
        float pd = x * r0i + y * r1i + z * r2i;
        float cx = y * r2i - z * r1i;
        float cy = z * r0i - x * r2i;
        float cz = x * r1i - y * r0i;
        float t1[3];
        t1[0] = r0i + Bc * cx + Cc * (x * pd - t2 * r0i);
        t1[1] = r1i + Bc * cy + Cc * (y * pd - t2 * r1i);
        t1[2] = r2i + Bc * cz + Cc * (z * pd - t2 * r2i);

        // ---- load target_T_inv row (top 3 rows of 4x4) ----
        const float4* Tp = (const float4*)(T + 16 * (long)b);
        float4 q0 = Tp[0], q1 = Tp[1], q2 = Tp[2];
        float Rt[9] = {q0.x, q0.y, q0.z, q1.x, q1.y, q1.z, q2.x, q2.y, q2.z};
        float tt[3] = {q0.w, q1.w, q2.w};

        // ---- compose: M = R1 @ Rt ; tm = R1 @ tt + t1 ----
        float M[9], tm[3];
        #pragma unroll
        for (int i = 0; i < 3; i++) {
            #pragma unroll
            for (int j = 0; j < 3; j++) {
                M[i * 3 + j] = R1[i * 3 + 0] * Rt[0 + j]
                             + R1[i * 3 + 1] * Rt[3 + j]
                             + R1[i * 3 + 2] * Rt[6 + j];
            }
            tm[i] = R1[i * 3 + 0] * tt[0] + R1[i * 3 + 1] * tt[1]
                  + R1[i * 3 + 2] * tt[2] + t1[i];
        }

        // ---- logs ----
        float xg[6], xs[6];
        se3_log_f(M, tm, xg);     // g_xi
        se3_log_f(Rt, tt, xs);    // xi_star

        // ---- quadratic forms ----
        float qg = 0.0f, qs = 0.0f;
        #pragma unroll
        for (int i = 0; i < 6; i++) {
            float yg = 0.0f, ys = 0.0f;
            #pragma unroll
            for (int j = 0; j < 6; j++) {
                yg = fmaf(sP[i * 6 + j], xg[j], yg);
                ys = fmaf(sP[i * 6 + j], xs[j], ys);
            }
            qg = fmaf(xg[i], yg, qg);
            qs = fmaf(xs[i], ys, qs);
        }
        acc += (double)qg - (double)qs;
    }

    // ---- block reduction ----
    acc = warpReduceD(acc);
    __shared__ double sw[NTHREADS / 32];
    if ((threadIdx.x & 31) == 0) sw[threadIdx.x >> 5] = acc;
    __syncthreads();
    if (threadIdx.x < 32) {
        double v = (threadIdx.x < NTHREADS / 32) ? sw[threadIdx.x] : 0.0;
        v = warpReduceD(v);
        if (threadIdx.x == 0) g_partials[blockIdx.x] = v;
    }
}

__global__ void __launch_bounds__(256)
se3_loss_finish(float* __restrict__ out, int B) {
    double v = 0.0;
    for (int i = threadIdx.x; i < NBLOCKS; i += 256)
        v += g_partials[i];
    v = warpReduceD(v);
    __shared__ double sw[8];
    if ((threadIdx.x & 31) == 0) sw[threadIdx.x >> 5] = v;
    __syncthreads();
    if (threadIdx.x < 32) {
        double t = (threadIdx.x < 8) ? sw[threadIdx.x] : 0.0;
        t = warpReduceD(t);
        if (threadIdx.x == 0)
            out[0] = (float)(0.5 / (double)B * t);
    }
}

extern "C" void kernel_launch(void* const* d_in, const int* in_sizes, int n_in,
                              void* d_out, int out_size) {
    const float* inp = (const float*)d_in[0];        // (B, 6)
    const float* T   = (const float*)d_in[1];        // (B, 4, 4)
    const float* P   = (const float*)d_in[2];        // (6, 6)
    float* out = (float*)d_out;
    int B = in_sizes[0] / 6;
    se3_loss_main<<<NBLOCKS, NTHREADS>>>(inp, T, P, B);
    se3_loss_finish<<<1, 256>>>(out, B);
}